// round 15
// baseline (speedup 1.0000x reference)
#include <cuda_runtime.h>
#include <cuda_bf16.h>
#include <math.h>
#include <stdint.h>

#define NB 16
#define NN 1024
#define MM 1024
#define DK 512

// -------- device scratch (no allocations allowed) --------
__device__ float g_U[NB * NN];
__device__ float g_V[NB * MM];
__device__ float g_W[NB * NN];
__device__ float g_WT[NB * 3 * NN];
__device__ __align__(16) float2 g_P[NB * 64 * MM];   // (max, sum) col partials
// bf16 split operands, K-major: [b][n][k]
__device__ __align__(16) __nv_bfloat16 g_Ahi[NB * NN * DK];
__device__ __align__(16) __nv_bfloat16 g_Alo[NB * NN * DK];
__device__ __align__(16) __nv_bfloat16 g_Bhi[NB * MM * DK];
__device__ __align__(16) __nv_bfloat16 g_Blo[NB * MM * DK];

static __device__ __forceinline__ void cp16(uint32_t s, const void* g) {
    asm volatile("cp.async.cg.shared.global [%0], [%1], 16;\n" ::"r"(s), "l"(g));
}
#define CP_COMMIT() asm volatile("cp.async.commit_group;\n")
#define CP_WAIT1()  asm volatile("cp.async.wait_group 1;\n")
#define CP_WAIT0()  asm volatile("cp.async.wait_group 0;\n")

// 32-byte evict_last load (only legal width for L2 hints on this toolchain)
static __device__ __forceinline__ void ld_el8(const float* p, float4& a, float4& b) {
    uint32_t q0, q1, q2, q3, q4, q5, q6, q7;
    asm volatile(
        "ld.global.L2::evict_last.v8.b32 {%0,%1,%2,%3,%4,%5,%6,%7}, [%8];"
        : "=r"(q0), "=r"(q1), "=r"(q2), "=r"(q3),
          "=r"(q4), "=r"(q5), "=r"(q6), "=r"(q7)
        : "l"(p));
    a = make_float4(__uint_as_float(q0), __uint_as_float(q1),
                    __uint_as_float(q2), __uint_as_float(q3));
    b = make_float4(__uint_as_float(q4), __uint_as_float(q5),
                    __uint_as_float(q6), __uint_as_float(q7));
}

// ============================================================
// Transpose + bf16 split, packed uint32 stores.
// ============================================================
__global__ __launch_bounds__(256) void k_conv(const float* __restrict__ EA,
                                              const float* __restrict__ EB) {
    __shared__ float tile[32][33];
    const int which = blockIdx.z >> 4;
    const int b = blockIdx.z & 15;
    const float* E = which ? EB : EA;
    __nv_bfloat16* Hi = which ? g_Bhi : g_Ahi;
    __nv_bfloat16* Lo = which ? g_Blo : g_Alo;
    const int n0 = blockIdx.x << 5;
    const int d0 = blockIdx.y << 5;
    const int tx = threadIdx.x & 31;
    const int ty = threadIdx.x >> 5;
#pragma unroll
    for (int i = ty; i < 32; i += 8)
        tile[i][tx] = E[((long)b * DK + d0 + i) * NN + n0 + tx];
    __syncthreads();
#pragma unroll
    for (int it = threadIdx.x; it < 512; it += 256) {
        const int n = it >> 4;
        const int dp = it & 15;
        float x0 = tile[2 * dp][n];
        float x1 = tile[2 * dp + 1][n];
        __nv_bfloat16 h0 = __float2bfloat16(x0);
        __nv_bfloat16 h1 = __float2bfloat16(x1);
        float r0 = x0 - __bfloat162float(h0);
        float r1 = x1 - __bfloat162float(h1);
        __nv_bfloat16 l0 = __float2bfloat16(r0);
        __nv_bfloat16 l1 = __float2bfloat16(r1);
        long o = ((long)b * NN + n0 + n) * DK + d0 + 2 * dp;
        uint32_t hp, lp;
        {
            uint16_t a, bb;
            memcpy(&a, &h0, 2); memcpy(&bb, &h1, 2);
            hp = (uint32_t)a | ((uint32_t)bb << 16);
            memcpy(&a, &l0, 2); memcpy(&bb, &l1, 2);
            lp = (uint32_t)a | ((uint32_t)bb << 16);
        }
        *(uint32_t*)&Hi[o] = hp;
        *(uint32_t*)&Lo[o] = lp;
    }
}

// ============================================================
// mma.sync bf16x3 GEMM: 128x128 CTA tile, 2x4 warps, 64x32 warp tile,
// BK=32, 2-stage double buffer, 2 CTAs/SM, A-frag reuse. (round-12 best)
// ============================================================
#define ROWP2 80
#define TIL2 (128 * ROWP2)
#define STG2 (4 * TIL2)

static __device__ __forceinline__ void ldmx4(uint32_t addr, uint32_t& r0,
                                             uint32_t& r1, uint32_t& r2, uint32_t& r3) {
    asm volatile("ldmatrix.sync.aligned.m8n8.x4.shared.b16 {%0,%1,%2,%3}, [%4];"
                 : "=r"(r0), "=r"(r1), "=r"(r2), "=r"(r3) : "r"(addr));
}
static __device__ __forceinline__ void mma16816(float* c, const uint32_t* a,
                                                const uint32_t* bb) {
    asm volatile(
        "mma.sync.aligned.m16n8k16.row.col.f32.bf16.bf16.f32 "
        "{%0,%1,%2,%3}, {%4,%5,%6,%7}, {%8,%9}, {%0,%1,%2,%3};"
        : "+f"(c[0]), "+f"(c[1]), "+f"(c[2]), "+f"(c[3])
        : "r"(a[0]), "r"(a[1]), "r"(a[2]), "r"(a[3]), "r"(bb[0]), "r"(bb[1]));
}

__global__ __launch_bounds__(256, 2) void k_mma(const float* __restrict__ temp,
                                                float* __restrict__ C) {
    extern __shared__ char smem[];
    const uint32_t sb = (uint32_t)__cvta_generic_to_shared(smem);
    const int tid = threadIdx.x;
    const int wid = tid >> 5, lane = tid & 31;
    const int wr = wid >> 2;
    const int wc = wid & 3;
    const int b = blockIdx.z;
    const int n0 = blockIdx.y << 7;
    const int m0 = blockIdx.x << 7;

    const __nv_bfloat16* Ah = g_Ahi + ((long)b * NN + n0) * DK;
    const __nv_bfloat16* Al = g_Alo + ((long)b * NN + n0) * DK;
    const __nv_bfloat16* Bh = g_Bhi + ((long)b * MM + m0) * DK;
    const __nv_bfloat16* Bl = g_Blo + ((long)b * MM + m0) * DK;

    auto issue = [&](int stage, int k0) {
#pragma unroll
        for (int t = tid; t < 2048; t += 256) {
            const int tile = t >> 9;
            const int row = (t >> 2) & 127;
            const int ch = t & 3;
            const __nv_bfloat16* g =
                (tile == 0 ? Ah : tile == 1 ? Al : tile == 2 ? Bh : Bl) +
                (long)row * DK + k0 + ch * 8;
            cp16(sb + (uint32_t)(stage * STG2 + tile * TIL2 + row * ROWP2 + ch * 16), g);
        }
        CP_COMMIT();
    };

    float acc[4][4][4];
#pragma unroll
    for (int i = 0; i < 4; ++i)
#pragma unroll
        for (int j = 0; j < 4; ++j)
#pragma unroll
            for (int q = 0; q < 4; ++q) acc[i][j][q] = 0.f;

    const uint32_t aoff = (uint32_t)((lane & 15) * ROWP2 + ((lane >> 4) << 4));
    const int brow = (lane & 7) + ((lane >> 4) & 1) * 8;
    const uint32_t boff = (uint32_t)(brow * ROWP2 + (((lane >> 3) & 1) << 4));
    const int kcbase = wid & 1;

    uint32_t afr[4][4], bfrH[4][2], bfrL[4][2];

    auto ldA = [&](uint32_t tb, int kc) {
#pragma unroll
        for (int mt = 0; mt < 4; ++mt)
            ldmx4(tb + (uint32_t)((wr * 64 + mt * 16) * ROWP2 + kc * 32) + aoff,
                  afr[mt][0], afr[mt][1], afr[mt][2], afr[mt][3]);
    };
    auto ldB = [&](uint32_t tb, int kc, uint32_t bf[4][2]) {
#pragma unroll
        for (int p = 0; p < 2; ++p) {
            uint32_t r0, r1, r2, r3;
            ldmx4(tb + (uint32_t)((wc * 32 + p * 16) * ROWP2 + kc * 32) + boff,
                  r0, r1, r2, r3);
            bf[2 * p][0] = r0; bf[2 * p][1] = r1;
            bf[2 * p + 1][0] = r2; bf[2 * p + 1][1] = r3;
        }
    };
    auto domma = [&](uint32_t bf[4][2]) {
#pragma unroll
        for (int mt = 0; mt < 4; ++mt)
#pragma unroll
            for (int nt = 0; nt < 4; ++nt)
                mma16816(acc[mt][nt], afr[mt], bf[nt]);
    };

    issue(0, 0);
    int buf = 0;
#pragma unroll 1
    for (int it = 0; it < 16; ++it) {
        if (it + 1 < 16) {
            issue(buf ^ 1, (it + 1) * 32);
            CP_WAIT1();
        } else {
            CP_WAIT0();
        }
        __syncthreads();
        const uint32_t st = sb + (uint32_t)(buf * STG2);
#pragma unroll
        for (int k = 0; k < 2; ++k) {
            const int kc = k ^ kcbase;
            ldA(st, kc);
            ldB(st + 2 * TIL2, kc, bfrH);
            ldB(st + 3 * TIL2, kc, bfrL);
            domma(bfrH);
            domma(bfrL);
            ldA(st + TIL2, kc);
            domma(bfrH);
        }
        __syncthreads();
        buf ^= 1;
    }

    const float sc = 1.0f / (sqrtf((float)DK) * temp[b]);
    const int ib = wr * 64 + (lane >> 2);
    const int jb = wc * 32 + (lane & 3) * 2;
#pragma unroll
    for (int mt = 0; mt < 4; ++mt)
#pragma unroll
        for (int nt = 0; nt < 4; ++nt) {
            long base = (((long)(b << 10) + n0 + ib + mt * 16) << 10) + m0 + jb + nt * 8;
            *(float2*)&C[base] =
                make_float2(acc[mt][nt][0] * sc, acc[mt][nt][1] * sc);
            *(float2*)&C[base + (8 << 10)] =
                make_float2(acc[mt][nt][2] * sc, acc[mt][nt][3] * sc);
        }
}

// ============================================================
// Fused sinkhorn iteration: row-LSE + column partials, one matrix read.
// Thread owns 8 cols x 8 rows; 32B evict_last loads keep matrix in L2.
// ============================================================
__global__ __launch_bounds__(256) void k_fused(const float* __restrict__ C, int first) {
    const int seg = blockIdx.x;   // 0..63
    const int b = blockIdx.y;     // 0..15
    const int t = threadIdx.x;    // 256
    const int tt = t & 127;       // column group (8 cols)
    const int grp = t >> 7;       // row half (rows 0-7 / 8-15)
    const int wid = t >> 5, lane = t & 31;
    __shared__ float4 V4s[256];
    __shared__ float2 red2[16][128];
    __shared__ float2 cpart[2][1024];
    __shared__ float Us[16];

    V4s[t] = first ? make_float4(0.f, 0.f, 0.f, 0.f)
                   : ((const float4*)(g_V + (b << 10)))[t];
    __syncthreads();
    const float4 vA = V4s[2 * tt];
    const float4 vB = V4s[2 * tt + 1];

    const int r0 = grp << 3;
    const int c0 = tt << 3;
    const float* base = C + ((long)b << 20) + ((long)seg << 14) + c0;
    float4 xa[8], xb[8];
#pragma unroll
    for (int i = 0; i < 8; ++i) {
        float4 a, bb;
        ld_el8(base + ((long)(r0 + i) << 10), a, bb);
        xa[i] = make_float4(a.x + vA.x, a.y + vA.y, a.z + vA.z, a.w + vA.w);
        xb[i] = make_float4(bb.x + vB.x, bb.y + vB.y, bb.z + vB.z, bb.w + vB.w);
        float tm = fmaxf(fmaxf(fmaxf(xa[i].x, xa[i].y), fmaxf(xa[i].z, xa[i].w)),
                         fmaxf(fmaxf(xb[i].x, xb[i].y), fmaxf(xb[i].z, xb[i].w)));
        float ts = __expf(xa[i].x - tm) + __expf(xa[i].y - tm) +
                   __expf(xa[i].z - tm) + __expf(xa[i].w - tm) +
                   __expf(xb[i].x - tm) + __expf(xb[i].y - tm) +
                   __expf(xb[i].z - tm) + __expf(xb[i].w - tm);
        red2[r0 + i][tt] = make_float2(tm, ts);
    }
    __syncthreads();

    // warp w reduces rows 2w, 2w+1 (128 partials each: 4/lane + shfl)
#pragma unroll
    for (int rr = 0; rr < 2; ++rr) {
        const int r = 2 * wid + rr;
        float2 p0 = red2[r][lane];
        float2 p1 = red2[r][lane + 32];
        float2 p2 = red2[r][lane + 64];
        float2 p3 = red2[r][lane + 96];
        float M = fmaxf(fmaxf(p0.x, p1.x), fmaxf(p2.x, p3.x));
        float S = p0.y * __expf(p0.x - M) + p1.y * __expf(p1.x - M) +
                  p2.y * __expf(p2.x - M) + p3.y * __expf(p3.x - M);
#pragma unroll
        for (int o = 16; o; o >>= 1) {
            float om = __shfl_xor_sync(0xffffffffu, M, o);
            float os = __shfl_xor_sync(0xffffffffu, S, o);
            float n = fmaxf(M, om);
            S = S * __expf(M - n) + os * __expf(om - n);
            M = n;
        }
        if (lane == 0) {
            float nm = fmaxf(M, 0.f);                 // slack col
            float S2 = S * __expf(M - nm) + __expf(-nm);
            float u = -(nm + logf(S2));
            Us[r] = u;
            g_U[(b << 10) + (seg << 4) + r] = u;
        }
    }
    __syncthreads();

    // column partials over this thread's 8 rows with new u
    float u0 = Us[r0];
    float4 Ma = make_float4(xa[0].x + u0, xa[0].y + u0, xa[0].z + u0, xa[0].w + u0);
    float4 Mb = make_float4(xb[0].x + u0, xb[0].y + u0, xb[0].z + u0, xb[0].w + u0);
#pragma unroll
    for (int i = 1; i < 8; ++i) {
        float u = Us[r0 + i];
        Ma.x = fmaxf(Ma.x, xa[i].x + u); Ma.y = fmaxf(Ma.y, xa[i].y + u);
        Ma.z = fmaxf(Ma.z, xa[i].z + u); Ma.w = fmaxf(Ma.w, xa[i].w + u);
        Mb.x = fmaxf(Mb.x, xb[i].x + u); Mb.y = fmaxf(Mb.y, xb[i].y + u);
        Mb.z = fmaxf(Mb.z, xb[i].z + u); Mb.w = fmaxf(Mb.w, xb[i].w + u);
    }
    float4 Sa = make_float4(0.f, 0.f, 0.f, 0.f);
    float4 Sb = make_float4(0.f, 0.f, 0.f, 0.f);
#pragma unroll
    for (int i = 0; i < 8; ++i) {
        float u = Us[r0 + i];
        Sa.x += __expf(xa[i].x + u - Ma.x); Sa.y += __expf(xa[i].y + u - Ma.y);
        Sa.z += __expf(xa[i].z + u - Ma.z); Sa.w += __expf(xa[i].w + u - Ma.w);
        Sb.x += __expf(xb[i].x + u - Mb.x); Sb.y += __expf(xb[i].y + u - Mb.y);
        Sb.z += __expf(xb[i].z + u - Mb.z); Sb.w += __expf(xb[i].w + u - Mb.w);
    }
    cpart[grp][c0 + 0] = make_float2(Ma.x, Sa.x);
    cpart[grp][c0 + 1] = make_float2(Ma.y, Sa.y);
    cpart[grp][c0 + 2] = make_float2(Ma.z, Sa.z);
    cpart[grp][c0 + 3] = make_float2(Ma.w, Sa.w);
    cpart[grp][c0 + 4] = make_float2(Mb.x, Sb.x);
    cpart[grp][c0 + 5] = make_float2(Mb.y, Sb.y);
    cpart[grp][c0 + 6] = make_float2(Mb.z, Sb.z);
    cpart[grp][c0 + 7] = make_float2(Mb.w, Sb.w);
    __syncthreads();

    // combine the 2 row-halves; write packed (m - v, s)
    const float4 vme = V4s[t];
    const float vv[4] = {vme.x, vme.y, vme.z, vme.w};
    float om[4], os[4];
#pragma unroll
    for (int j = 0; j < 4; ++j) {
        const int col = 4 * t + j;
        float2 a = cpart[0][col];
        float2 bb = cpart[1][col];
        float n = fmaxf(a.x, bb.x);
        float s = a.y * __expf(a.x - n) + bb.y * __expf(bb.x - n);
        om[j] = n - vv[j];
        os[j] = s;
    }
    const long p4 = (((long)(b << 6) + seg) << 9) + (t << 1);
    ((float4*)g_P)[p4] = make_float4(om[0], os[0], om[1], os[1]);
    ((float4*)g_P)[p4 + 1] = make_float4(om[2], os[2], om[3], os[3]);
}

// ============================================================
// Combine 64 segment partials per column: grid (32, NB) x 256.
// ============================================================
__global__ __launch_bounds__(256) void k_colr() {
    const int b = blockIdx.y;
    const int c = threadIdx.x & 31;
    const int q = threadIdx.x >> 5;
    const int j = (blockIdx.x << 5) + c;
    __shared__ float Msm[8][32], Ssm[8][32];

    float mv[8], sv[8];
#pragma unroll
    for (int g = 0; g < 8; ++g) {
        const long p = (((long)(b << 6) + (q << 3) + g) << 10) + j;
        float2 ms = g_P[p];
        mv[g] = ms.x;
        sv[g] = ms.y;
    }
    float M = mv[0];
#pragma unroll
    for (int g = 1; g < 8; ++g) M = fmaxf(M, mv[g]);
    float S = 0.f;
#pragma unroll
    for (int g = 0; g < 8; ++g) S += sv[g] * __expf(mv[g] - M);
    Msm[q][c] = M;
    Ssm[q][c] = S;
    __syncthreads();
    if (q == 0) {
        float m2[8], s2[8];
#pragma unroll
        for (int g = 0; g < 8; ++g) { m2[g] = Msm[g][c]; s2[g] = Ssm[g][c]; }
        float MM2 = m2[0];
#pragma unroll
        for (int g = 1; g < 8; ++g) MM2 = fmaxf(MM2, m2[g]);
        MM2 = fmaxf(MM2, 0.f);
        float SS = __expf(-MM2);
#pragma unroll
        for (int g = 0; g < 8; ++g) SS += s2[g] * __expf(m2[g] - MM2);
        g_V[(b << 10) + j] = -(MM2 + logf(SS));
    }
}

// ============================================================
// Finalize
// ============================================================
__global__ __launch_bounds__(256) void k_final(float* __restrict__ C,
                                               const float* __restrict__ tgt) {
    const int gb = blockIdx.x;
    const int b = gb >> 7;
    const int row = ((gb & 127) << 3) + (threadIdx.x >> 5);
    const int lane = threadIdx.x & 31;
    __shared__ float4 Vs4[256], T04[256], T14[256], T24[256];
    const float* tb = tgt + (long)b * 3 * MM;
    Vs4[threadIdx.x] = ((const float4*)(g_V + (b << 10)))[threadIdx.x];
    T04[threadIdx.x] = ((const float4*)tb)[threadIdx.x];
    T14[threadIdx.x] = ((const float4*)(tb + MM))[threadIdx.x];
    T24[threadIdx.x] = ((const float4*)(tb + 2 * MM))[threadIdx.x];
    __syncthreads();
    float4* rp = (float4*)(C + (((long)(b << 10) + row) << 10));
    const float u = g_U[(b << 10) + row];
    float4 p[8];
    float s0 = 0.f, s1 = 0.f, s2 = 0.f, s3 = 0.f;
#pragma unroll
    for (int k = 0; k < 8; ++k) {
        float4 c = rp[lane + (k << 5)];
        float4 v = Vs4[lane + (k << 5)];
        p[k].x = __expf(c.x + u + v.x);
        p[k].y = __expf(c.y + u + v.y);
        p[k].z = __expf(c.z + u + v.z);
        p[k].w = __expf(c.w + u + v.w);
        s0 += p[k].x; s1 += p[k].y; s2 += p[k].z; s3 += p[k].w;
    }
    float sum = (s0 + s1) + (s2 + s3);
#pragma unroll
    for (int o = 16; o; o >>= 1) sum += __shfl_xor_sync(0xffffffffu, sum, o);
    const float inv = 1.f / (sum + 1e-8f);
    float w0 = 0.f, w1 = 0.f, w2 = 0.f;
#pragma unroll
    for (int k = 0; k < 8; ++k) {
        int j4 = lane + (k << 5);
        float4 pn = make_float4(p[k].x * inv, p[k].y * inv, p[k].z * inv, p[k].w * inv);
        rp[j4] = pn;
        float4 t0 = T04[j4], t1 = T14[j4], t2 = T24[j4];
        w0 = fmaf(pn.x, t0.x, fmaf(pn.y, t0.y, fmaf(pn.z, t0.z, fmaf(pn.w, t0.w, w0))));
        w1 = fmaf(pn.x, t1.x, fmaf(pn.y, t1.y, fmaf(pn.z, t1.z, fmaf(pn.w, t1.w, w1))));
        w2 = fmaf(pn.x, t2.x, fmaf(pn.y, t2.y, fmaf(pn.z, t2.z, fmaf(pn.w, t2.w, w2))));
    }
#pragma unroll
    for (int o = 16; o; o >>= 1) {
        w0 += __shfl_xor_sync(0xffffffffu, w0, o);
        w1 += __shfl_xor_sync(0xffffffffu, w1, o);
        w2 += __shfl_xor_sync(0xffffffffu, w2, o);
    }
    if (lane == 0) {
        g_W[(b << 10) + row] = sum;
        g_WT[b * 3 * NN + row] = w0;
        g_WT[b * 3 * NN + NN + row] = w1;
        g_WT[b * 3 * NN + 2 * NN + row] = w2;
    }
}

// ============================================================
// Per-batch weighted Procrustes (Horn quaternion via 4x4 Jacobi, fp64).
// ============================================================
__global__ __launch_bounds__(256) void k_proc(const float* __restrict__ src,
                                              float* __restrict__ out) {
    const int b = blockIdx.x;
    const int tid = threadIdx.x;
    __shared__ float sm[256 * 12];
    __shared__ float cent[8];
    const float* sb = src + (long)b * 3 * NN;
    const float* wb = g_W + (b << 10);
    const float* wtb = g_WT + b * 3 * NN;

    float ws = 0, s0 = 0, s1 = 0, s2 = 0, t0 = 0, t1 = 0, t2 = 0;
    for (int i = tid; i < NN; i += 256) {
        float w = wb[i];
        ws += w;
        s0 = fmaf(sb[i], w, s0);
        s1 = fmaf(sb[NN + i], w, s1);
        s2 = fmaf(sb[2 * NN + i], w, s2);
        t0 = fmaf(wtb[i], w, t0);
        t1 = fmaf(wtb[NN + i], w, t1);
        t2 = fmaf(wtb[2 * NN + i], w, t2);
    }
    sm[tid * 12 + 0] = ws; sm[tid * 12 + 1] = s0; sm[tid * 12 + 2] = s1;
    sm[tid * 12 + 3] = s2; sm[tid * 12 + 4] = t0; sm[tid * 12 + 5] = t1;
    sm[tid * 12 + 6] = t2;
    __syncthreads();
    for (int st = 128; st; st >>= 1) {
        if (tid < st)
            for (int k = 0; k < 7; ++k) sm[tid * 12 + k] += sm[(tid + st) * 12 + k];
        __syncthreads();
    }
    if (tid == 0) {
        float inv = 1.f / (sm[0] + 1e-8f);
        cent[6] = inv;
        for (int c = 0; c < 3; ++c) { cent[c] = sm[1 + c] * inv; cent[3 + c] = sm[4 + c] * inv; }
    }
    __syncthreads();
    const float inv = cent[6];
    const float sc0 = cent[0], sc1 = cent[1], sc2 = cent[2];
    const float tc0 = cent[3], tc1 = cent[4], tc2 = cent[5];

    float h[9];
#pragma unroll
    for (int k = 0; k < 9; ++k) h[k] = 0.f;
    for (int i = tid; i < NN; i += 256) {
        float wn = wb[i] * inv;
        float a0 = sb[i] - sc0, a1 = sb[NN + i] - sc1, a2 = sb[2 * NN + i] - sc2;
        float b0 = (wtb[i] - tc0) * wn;
        float b1 = (wtb[NN + i] - tc1) * wn;
        float b2 = (wtb[2 * NN + i] - tc2) * wn;
        h[0] = fmaf(a0, b0, h[0]); h[1] = fmaf(a0, b1, h[1]); h[2] = fmaf(a0, b2, h[2]);
        h[3] = fmaf(a1, b0, h[3]); h[4] = fmaf(a1, b1, h[4]); h[5] = fmaf(a1, b2, h[5]);
        h[6] = fmaf(a2, b0, h[6]); h[7] = fmaf(a2, b1, h[7]); h[8] = fmaf(a2, b2, h[8]);
    }
    __syncthreads();
    for (int k = 0; k < 9; ++k) sm[tid * 12 + k] = h[k];
    __syncthreads();
    for (int st = 128; st; st >>= 1) {
        if (tid < st)
            for (int k = 0; k < 9; ++k) sm[tid * 12 + k] += sm[(tid + st) * 12 + k];
        __syncthreads();
    }

    if (tid == 0) {
        double Sxx = sm[0], Sxy = sm[1], Sxz = sm[2];
        double Syx = sm[3], Syy = sm[4], Syz = sm[5];
        double Szx = sm[6], Szy = sm[7], Szz = sm[8];
        double A4[4][4], V4[4][4];
        A4[0][0] = Sxx + Syy + Szz;
        A4[0][1] = Syz - Szy; A4[0][2] = Szx - Sxz; A4[0][3] = Sxy - Syx;
        A4[1][1] = Sxx - Syy - Szz;
        A4[1][2] = Sxy + Syx; A4[1][3] = Szx + Sxz;
        A4[2][2] = -Sxx + Syy - Szz;
        A4[2][3] = Syz + Szy;
        A4[3][3] = -Sxx - Syy + Szz;
        A4[1][0] = A4[0][1]; A4[2][0] = A4[0][2]; A4[3][0] = A4[0][3];
        A4[2][1] = A4[1][2]; A4[3][1] = A4[1][3]; A4[3][2] = A4[2][3];
        for (int i = 0; i < 4; ++i)
            for (int j = 0; j < 4; ++j) V4[i][j] = (i == j) ? 1.0 : 0.0;
        for (int sw = 0; sw < 8; ++sw) {
            for (int p = 0; p < 3; ++p)
                for (int q = p + 1; q < 4; ++q) {
                    double apq = A4[p][q];
                    if (fabs(apq) < 1e-300) continue;
                    double tau = (A4[q][q] - A4[p][p]) / (2.0 * apq);
                    double tt = (tau >= 0 ? 1.0 : -1.0) / (fabs(tau) + sqrt(1.0 + tau * tau));
                    double cc = 1.0 / sqrt(1.0 + tt * tt);
                    double ssn = tt * cc;
                    for (int k = 0; k < 4; ++k) {
                        double r1 = A4[p][k], r2 = A4[q][k];
                        A4[p][k] = cc * r1 - ssn * r2;
                        A4[q][k] = ssn * r1 + cc * r2;
                    }
                    for (int k = 0; k < 4; ++k) {
                        double c1 = A4[k][p], c2 = A4[k][q];
                        A4[k][p] = cc * c1 - ssn * c2;
                        A4[k][q] = ssn * c1 + cc * c2;
                    }
                    for (int k = 0; k < 4; ++k) {
                        double v1 = V4[k][p], v2 = V4[k][q];
                        V4[k][p] = cc * v1 - ssn * v2;
                        V4[k][q] = ssn * v1 + cc * v2;
                    }
                }
        }
        int best = 0;
        for (int k = 1; k < 4; ++k) if (A4[k][k] > A4[best][best]) best = k;
        double q0 = V4[0][best], qx = V4[1][best], qy = V4[2][best], qz = V4[3][best];
        double qn = 1.0 / sqrt(q0 * q0 + qx * qx + qy * qy + qz * qz);
        q0 *= qn; qx *= qn; qy *= qn; qz *= qn;
        double R_[3][3];
        R_[0][0] = 1 - 2 * (qy * qy + qz * qz);
        R_[0][1] = 2 * (qx * qy - q0 * qz);
        R_[0][2] = 2 * (qx * qz + q0 * qy);
        R_[1][0] = 2 * (qx * qy + q0 * qz);
        R_[1][1] = 1 - 2 * (qx * qx + qz * qz);
        R_[1][2] = 2 * (qy * qz - q0 * qx);
        R_[2][0] = 2 * (qx * qz - q0 * qy);
        R_[2][1] = 2 * (qy * qz + q0 * qx);
        R_[2][2] = 1 - 2 * (qx * qx + qy * qy);
        double H_[3][3] = {{Sxx, Sxy, Sxz}, {Syx, Syy, Syz}, {Szx, Szy, Szz}};
        double tr1 = 0, tr2 = 0;
        for (int i = 0; i < 3; ++i)
            for (int k = 0; k < 3; ++k) {
                tr1 += R_[i][k] * H_[k][i];
                tr2 += R_[k][i] * H_[k][i];
            }
        if (tr2 > tr1) {
            for (int i = 0; i < 3; ++i)
                for (int k = i + 1; k < 3; ++k) {
                    double tmp = R_[i][k]; R_[i][k] = R_[k][i]; R_[k][i] = tmp;
                }
        }
        double scv[3] = {sc0, sc1, sc2}, tcv[3] = {tc0, tc1, tc2};
        for (int i = 0; i < 3; ++i)
            for (int k = 0; k < 3; ++k)
                out[b * 9 + i * 3 + k] = (float)R_[i][k];
        for (int c = 0; c < 3; ++c) {
            double tv = tcv[c];
            for (int k = 0; k < 3; ++k) tv -= R_[c][k] * scv[k];
            out[NB * 9 + b * 3 + c] = (float)tv;
        }
    }
}

// ============================================================
extern "C" void kernel_launch(void* const* d_in, const int* in_sizes, int n_in,
                              void* d_out, int out_size) {
    const float* srcE = (const float*)d_in[0];
    const float* tgtE = (const float*)d_in[1];
    const float* src  = (const float*)d_in[2];
    const float* tgt  = (const float*)d_in[3];
    const float* temp = (const float*)d_in[4];
    float* out = (float*)d_out;
    float* aff = out + NB * 9 + NB * 3;

    (void)in_sizes; (void)n_in; (void)out_size;

    const int SMEM_SZ = 2 * STG2;   // 81920 per CTA -> 2 CTAs/SM
    static int configured = 0;
    if (!configured) {
        cudaFuncSetAttribute(k_mma, cudaFuncAttributeMaxDynamicSharedMemorySize, SMEM_SZ);
        configured = 1;
    }

    k_conv<<<dim3(32, 16, 32), 256>>>(srcE, tgtE);
    k_mma<<<dim3(8, 8, NB), 256, SMEM_SZ>>>(temp, aff);
    for (int it = 0; it < 5; ++it) {
        k_fused<<<dim3(64, NB), 256>>>(aff, it == 0);
        k_colr<<<dim3(32, NB), 256>>>();
    }
    k_final<<<2048, 256>>>(aff, tgt);
    k_proc<<<NB, 256>>>(src, out);
}

// round 16
// speedup vs baseline: 1.0193x; 1.0193x over previous
#include <cuda_runtime.h>
#include <cuda_bf16.h>
#include <math.h>
#include <stdint.h>

#define NB 16
#define NN 1024
#define MM 1024
#define DK 512

// -------- device scratch (no allocations allowed) --------
__device__ float g_U[NB * NN];
__device__ float g_V[NB * MM];
__device__ float g_W[NB * NN];
__device__ float g_WT[NB * 3 * NN];
__device__ __align__(16) float2 g_P[NB * 64 * MM];   // (max, sum) col partials
// bf16 split operands, K-major: [b][n][k]
__device__ __align__(16) __nv_bfloat16 g_Ahi[NB * NN * DK];
__device__ __align__(16) __nv_bfloat16 g_Alo[NB * NN * DK];
__device__ __align__(16) __nv_bfloat16 g_Bhi[NB * MM * DK];
__device__ __align__(16) __nv_bfloat16 g_Blo[NB * MM * DK];

static __device__ __forceinline__ void cp16(uint32_t s, const void* g) {
    asm volatile("cp.async.cg.shared.global [%0], [%1], 16;\n" ::"r"(s), "l"(g));
}
#define CP_COMMIT() asm volatile("cp.async.commit_group;\n")
#define CP_WAIT1()  asm volatile("cp.async.wait_group 1;\n")
#define CP_WAIT0()  asm volatile("cp.async.wait_group 0;\n")

// ============================================================
// Transpose + bf16 split, packed uint32 stores.
// ============================================================
__global__ __launch_bounds__(256) void k_conv(const float* __restrict__ EA,
                                              const float* __restrict__ EB) {
    __shared__ float tile[32][33];
    const int which = blockIdx.z >> 4;
    const int b = blockIdx.z & 15;
    const float* E = which ? EB : EA;
    __nv_bfloat16* Hi = which ? g_Bhi : g_Ahi;
    __nv_bfloat16* Lo = which ? g_Blo : g_Alo;
    const int n0 = blockIdx.x << 5;
    const int d0 = blockIdx.y << 5;
    const int tx = threadIdx.x & 31;
    const int ty = threadIdx.x >> 5;
#pragma unroll
    for (int i = ty; i < 32; i += 8)
        tile[i][tx] = E[((long)b * DK + d0 + i) * NN + n0 + tx];
    __syncthreads();
#pragma unroll
    for (int it = threadIdx.x; it < 512; it += 256) {
        const int n = it >> 4;
        const int dp = it & 15;
        float x0 = tile[2 * dp][n];
        float x1 = tile[2 * dp + 1][n];
        __nv_bfloat16 h0 = __float2bfloat16(x0);
        __nv_bfloat16 h1 = __float2bfloat16(x1);
        float r0 = x0 - __bfloat162float(h0);
        float r1 = x1 - __bfloat162float(h1);
        __nv_bfloat16 l0 = __float2bfloat16(r0);
        __nv_bfloat16 l1 = __float2bfloat16(r1);
        long o = ((long)b * NN + n0 + n) * DK + d0 + 2 * dp;
        uint32_t hp, lp;
        {
            uint16_t a, bb;
            memcpy(&a, &h0, 2); memcpy(&bb, &h1, 2);
            hp = (uint32_t)a | ((uint32_t)bb << 16);
            memcpy(&a, &l0, 2); memcpy(&bb, &l1, 2);
            lp = (uint32_t)a | ((uint32_t)bb << 16);
        }
        *(uint32_t*)&Hi[o] = hp;
        *(uint32_t*)&Lo[o] = lp;
    }
}

// ============================================================
// mma.sync bf16x3 GEMM: 128x128 CTA tile, 2x4 warps, 64x32 warp tile,
// BK=32, 2-stage double buffer, 2 CTAs/SM, A-frag reuse. (round-12 best)
// ============================================================
#define ROWP2 80
#define TIL2 (128 * ROWP2)
#define STG2 (4 * TIL2)

static __device__ __forceinline__ void ldmx4(uint32_t addr, uint32_t& r0,
                                             uint32_t& r1, uint32_t& r2, uint32_t& r3) {
    asm volatile("ldmatrix.sync.aligned.m8n8.x4.shared.b16 {%0,%1,%2,%3}, [%4];"
                 : "=r"(r0), "=r"(r1), "=r"(r2), "=r"(r3) : "r"(addr));
}
static __device__ __forceinline__ void mma16816(float* c, const uint32_t* a,
                                                const uint32_t* bb) {
    asm volatile(
        "mma.sync.aligned.m16n8k16.row.col.f32.bf16.bf16.f32 "
        "{%0,%1,%2,%3}, {%4,%5,%6,%7}, {%8,%9}, {%0,%1,%2,%3};"
        : "+f"(c[0]), "+f"(c[1]), "+f"(c[2]), "+f"(c[3])
        : "r"(a[0]), "r"(a[1]), "r"(a[2]), "r"(a[3]), "r"(bb[0]), "r"(bb[1]));
}

__global__ __launch_bounds__(256, 2) void k_mma(const float* __restrict__ temp,
                                                float* __restrict__ C) {
    extern __shared__ char smem[];
    const uint32_t sb = (uint32_t)__cvta_generic_to_shared(smem);
    const int tid = threadIdx.x;
    const int wid = tid >> 5, lane = tid & 31;
    const int wr = wid >> 2;
    const int wc = wid & 3;
    const int b = blockIdx.z;
    const int n0 = blockIdx.y << 7;
    const int m0 = blockIdx.x << 7;

    const __nv_bfloat16* Ah = g_Ahi + ((long)b * NN + n0) * DK;
    const __nv_bfloat16* Al = g_Alo + ((long)b * NN + n0) * DK;
    const __nv_bfloat16* Bh = g_Bhi + ((long)b * MM + m0) * DK;
    const __nv_bfloat16* Bl = g_Blo + ((long)b * MM + m0) * DK;

    auto issue = [&](int stage, int k0) {
#pragma unroll
        for (int t = tid; t < 2048; t += 256) {
            const int tile = t >> 9;
            const int row = (t >> 2) & 127;
            const int ch = t & 3;
            const __nv_bfloat16* g =
                (tile == 0 ? Ah : tile == 1 ? Al : tile == 2 ? Bh : Bl) +
                (long)row * DK + k0 + ch * 8;
            cp16(sb + (uint32_t)(stage * STG2 + tile * TIL2 + row * ROWP2 + ch * 16), g);
        }
        CP_COMMIT();
    };

    float acc[4][4][4];
#pragma unroll
    for (int i = 0; i < 4; ++i)
#pragma unroll
        for (int j = 0; j < 4; ++j)
#pragma unroll
            for (int q = 0; q < 4; ++q) acc[i][j][q] = 0.f;

    const uint32_t aoff = (uint32_t)((lane & 15) * ROWP2 + ((lane >> 4) << 4));
    const int brow = (lane & 7) + ((lane >> 4) & 1) * 8;
    const uint32_t boff = (uint32_t)(brow * ROWP2 + (((lane >> 3) & 1) << 4));
    const int kcbase = wid & 1;

    uint32_t afr[4][4], bfrH[4][2], bfrL[4][2];

    auto ldA = [&](uint32_t tb, int kc) {
#pragma unroll
        for (int mt = 0; mt < 4; ++mt)
            ldmx4(tb + (uint32_t)((wr * 64 + mt * 16) * ROWP2 + kc * 32) + aoff,
                  afr[mt][0], afr[mt][1], afr[mt][2], afr[mt][3]);
    };
    auto ldB = [&](uint32_t tb, int kc, uint32_t bf[4][2]) {
#pragma unroll
        for (int p = 0; p < 2; ++p) {
            uint32_t r0, r1, r2, r3;
            ldmx4(tb + (uint32_t)((wc * 32 + p * 16) * ROWP2 + kc * 32) + boff,
                  r0, r1, r2, r3);
            bf[2 * p][0] = r0; bf[2 * p][1] = r1;
            bf[2 * p + 1][0] = r2; bf[2 * p + 1][1] = r3;
        }
    };
    auto domma = [&](uint32_t bf[4][2]) {
#pragma unroll
        for (int mt = 0; mt < 4; ++mt)
#pragma unroll
            for (int nt = 0; nt < 4; ++nt)
                mma16816(acc[mt][nt], afr[mt], bf[nt]);
    };

    issue(0, 0);
    int buf = 0;
#pragma unroll 1
    for (int it = 0; it < 16; ++it) {
        if (it + 1 < 16) {
            issue(buf ^ 1, (it + 1) * 32);
            CP_WAIT1();
        } else {
            CP_WAIT0();
        }
        __syncthreads();
        const uint32_t st = sb + (uint32_t)(buf * STG2);
#pragma unroll
        for (int k = 0; k < 2; ++k) {
            const int kc = k ^ kcbase;
            ldA(st, kc);
            ldB(st + 2 * TIL2, kc, bfrH);
            ldB(st + 3 * TIL2, kc, bfrL);
            domma(bfrH);
            domma(bfrL);
            ldA(st + TIL2, kc);
            domma(bfrH);
        }
        __syncthreads();
        buf ^= 1;
    }

    const float sc = 1.0f / (sqrtf((float)DK) * temp[b]);
    const int ib = wr * 64 + (lane >> 2);
    const int jb = wc * 32 + (lane & 3) * 2;
#pragma unroll
    for (int mt = 0; mt < 4; ++mt)
#pragma unroll
        for (int nt = 0; nt < 4; ++nt) {
            long base = (((long)(b << 10) + n0 + ib + mt * 16) << 10) + m0 + jb + nt * 8;
            *(float2*)&C[base] =
                make_float2(acc[mt][nt][0] * sc, acc[mt][nt][1] * sc);
            *(float2*)&C[base + (8 << 10)] =
                make_float2(acc[mt][nt][2] * sc, acc[mt][nt][3] * sc);
        }
}

// ============================================================
// Fused sinkhorn iteration: row-LSE + column partials, one matrix read.
// (round-13 form: float4 layout, single-pass (m,s) reduction)
// ============================================================
__global__ __launch_bounds__(256) void k_fused(const float* __restrict__ C, int first) {
    const int seg = blockIdx.x;   // 0..63
    const int b = blockIdx.y;     // 0..15
    const int t = threadIdx.x;    // 256
    const int wid = t >> 5, lane = t & 31;
    __shared__ float4 V4s[256];
    __shared__ float2 red2[16][256];
    __shared__ float Us[16];

    V4s[t] = first ? make_float4(0.f, 0.f, 0.f, 0.f)
                   : ((const float4*)(g_V + (b << 10)))[t];
    __syncthreads();
    const float4 v4 = V4s[t];

    const float4* base = (const float4*)(C + ((long)b << 20) + ((long)seg << 14));
    float4 x[16];
#pragma unroll
    for (int i = 0; i < 16; ++i) {
        float4 c = base[(i << 8) + t];
        x[i] = make_float4(c.x + v4.x, c.y + v4.y, c.z + v4.z, c.w + v4.w);
    }

#pragma unroll
    for (int i = 0; i < 16; ++i) {
        float tm = fmaxf(fmaxf(x[i].x, x[i].y), fmaxf(x[i].z, x[i].w));
        float ts = __expf(x[i].x - tm) + __expf(x[i].y - tm) +
                   __expf(x[i].z - tm) + __expf(x[i].w - tm);
        red2[i][t] = make_float2(tm, ts);
    }
    __syncthreads();

#pragma unroll
    for (int rr = 0; rr < 2; ++rr) {
        const int r = 2 * wid + rr;
        float mm[8], ss[8];
#pragma unroll
        for (int k = 0; k < 8; ++k) {
            float2 p = red2[r][lane + 32 * k];
            mm[k] = p.x; ss[k] = p.y;
        }
        float M = mm[0];
#pragma unroll
        for (int k = 1; k < 8; ++k) M = fmaxf(M, mm[k]);
        float S = 0.f;
#pragma unroll
        for (int k = 0; k < 8; ++k) S += ss[k] * __expf(mm[k] - M);
#pragma unroll
        for (int o = 16; o; o >>= 1) {
            float om = __shfl_xor_sync(0xffffffffu, M, o);
            float os = __shfl_xor_sync(0xffffffffu, S, o);
            float n = fmaxf(M, om);
            S = S * __expf(M - n) + os * __expf(om - n);
            M = n;
        }
        if (lane == 0) {
            float nm = fmaxf(M, 0.f);
            float S2 = S * __expf(M - nm) + __expf(-nm);
            float u = -(nm + logf(S2));
            Us[r] = u;
            g_U[(b << 10) + (seg << 4) + r] = u;
        }
    }
    __syncthreads();

    float u0 = Us[0];
    float4 M4 = make_float4(x[0].x + u0, x[0].y + u0, x[0].z + u0, x[0].w + u0);
#pragma unroll
    for (int i = 1; i < 16; ++i) {
        float u = Us[i];
        M4.x = fmaxf(M4.x, x[i].x + u); M4.y = fmaxf(M4.y, x[i].y + u);
        M4.z = fmaxf(M4.z, x[i].z + u); M4.w = fmaxf(M4.w, x[i].w + u);
    }
    float4 S4 = make_float4(0.f, 0.f, 0.f, 0.f);
#pragma unroll
    for (int i = 0; i < 16; ++i) {
        float u = Us[i];
        S4.x += __expf(x[i].x + u - M4.x); S4.y += __expf(x[i].y + u - M4.y);
        S4.z += __expf(x[i].z + u - M4.z); S4.w += __expf(x[i].w + u - M4.w);
    }
    const long p4 = (((long)(b << 6) + seg) << 9) + (t << 1);
    ((float4*)g_P)[p4] = make_float4(M4.x - v4.x, S4.x, M4.y - v4.y, S4.y);
    ((float4*)g_P)[p4 + 1] = make_float4(M4.z - v4.z, S4.z, M4.w - v4.w, S4.w);
}

// ============================================================
// Combine 64 segment partials per column: grid (16, NB) x 256.
// Thread handles a COLUMN PAIR via float4 loads (2x wider requests).
// ============================================================
__global__ __launch_bounds__(256) void k_colr() {
    const int b = blockIdx.y;
    const int c = threadIdx.x & 31;          // col-pair within block (32 pairs)
    const int q = threadIdx.x >> 5;          // 0..7 : 8 segments each
    const int jp = (blockIdx.x << 5) + c;    // global col-pair 0..511
    __shared__ float2 Mm[8][64];             // (M,S) per column per q

    float m0[8], s0[8], m1[8], s1[8];
#pragma unroll
    for (int g = 0; g < 8; ++g) {
        const long p4 = ((long)((b << 6) + (q << 3) + g) << 9) + jp;
        float4 v = ((const float4*)g_P)[p4];
        m0[g] = v.x; s0[g] = v.y;
        m1[g] = v.z; s1[g] = v.w;
    }
    float M0 = m0[0], M1 = m1[0];
#pragma unroll
    for (int g = 1; g < 8; ++g) { M0 = fmaxf(M0, m0[g]); M1 = fmaxf(M1, m1[g]); }
    float S0 = 0.f, S1 = 0.f;
#pragma unroll
    for (int g = 0; g < 8; ++g) {
        S0 += s0[g] * __expf(m0[g] - M0);
        S1 += s1[g] * __expf(m1[g] - M1);
    }
    Mm[q][2 * c] = make_float2(M0, S0);
    Mm[q][2 * c + 1] = make_float2(M1, S1);
    __syncthreads();
    if (q < 2) {
        const int col = (q << 5) + c;        // 0..63
        float mv[8], sv[8];
#pragma unroll
        for (int g = 0; g < 8; ++g) {
            float2 ms = Mm[g][col];
            mv[g] = ms.x; sv[g] = ms.y;
        }
        float M = mv[0];
#pragma unroll
        for (int g = 1; g < 8; ++g) M = fmaxf(M, mv[g]);
        M = fmaxf(M, 0.f);                   // slack row
        float S = __expf(-M);
#pragma unroll
        for (int g = 0; g < 8; ++g) S += sv[g] * __expf(mv[g] - M);
        g_V[(b << 10) + (blockIdx.x << 6) + col] = -(M + logf(S));
    }
}

// ============================================================
// Finalize
// ============================================================
__global__ __launch_bounds__(256) void k_final(float* __restrict__ C,
                                               const float* __restrict__ tgt) {
    const int gb = blockIdx.x;
    const int b = gb >> 7;
    const int row = ((gb & 127) << 3) + (threadIdx.x >> 5);
    const int lane = threadIdx.x & 31;
    __shared__ float4 Vs4[256], T04[256], T14[256], T24[256];
    const float* tb = tgt + (long)b * 3 * MM;
    Vs4[threadIdx.x] = ((const float4*)(g_V + (b << 10)))[threadIdx.x];
    T04[threadIdx.x] = ((const float4*)tb)[threadIdx.x];
    T14[threadIdx.x] = ((const float4*)(tb + MM))[threadIdx.x];
    T24[threadIdx.x] = ((const float4*)(tb + 2 * MM))[threadIdx.x];
    __syncthreads();
    float4* rp = (float4*)(C + (((long)(b << 10) + row) << 10));
    const float u = g_U[(b << 10) + row];
    float4 p[8];
    float s0 = 0.f, s1 = 0.f, s2 = 0.f, s3 = 0.f;
#pragma unroll
    for (int k = 0; k < 8; ++k) {
        float4 c = rp[lane + (k << 5)];
        float4 v = Vs4[lane + (k << 5)];
        p[k].x = __expf(c.x + u + v.x);
        p[k].y = __expf(c.y + u + v.y);
        p[k].z = __expf(c.z + u + v.z);
        p[k].w = __expf(c.w + u + v.w);
        s0 += p[k].x; s1 += p[k].y; s2 += p[k].z; s3 += p[k].w;
    }
    float sum = (s0 + s1) + (s2 + s3);
#pragma unroll
    for (int o = 16; o; o >>= 1) sum += __shfl_xor_sync(0xffffffffu, sum, o);
    const float inv = 1.f / (sum + 1e-8f);
    float w0 = 0.f, w1 = 0.f, w2 = 0.f;
#pragma unroll
    for (int k = 0; k < 8; ++k) {
        int j4 = lane + (k << 5);
        float4 pn = make_float4(p[k].x * inv, p[k].y * inv, p[k].z * inv, p[k].w * inv);
        rp[j4] = pn;
        float4 t0 = T04[j4], t1 = T14[j4], t2 = T24[j4];
        w0 = fmaf(pn.x, t0.x, fmaf(pn.y, t0.y, fmaf(pn.z, t0.z, fmaf(pn.w, t0.w, w0))));
        w1 = fmaf(pn.x, t1.x, fmaf(pn.y, t1.y, fmaf(pn.z, t1.z, fmaf(pn.w, t1.w, w1))));
        w2 = fmaf(pn.x, t2.x, fmaf(pn.y, t2.y, fmaf(pn.z, t2.z, fmaf(pn.w, t2.w, w2))));
    }
#pragma unroll
    for (int o = 16; o; o >>= 1) {
        w0 += __shfl_xor_sync(0xffffffffu, w0, o);
        w1 += __shfl_xor_sync(0xffffffffu, w1, o);
        w2 += __shfl_xor_sync(0xffffffffu, w2, o);
    }
    if (lane == 0) {
        g_W[(b << 10) + row] = sum;
        g_WT[b * 3 * NN + row] = w0;
        g_WT[b * 3 * NN + NN + row] = w1;
        g_WT[b * 3 * NN + 2 * NN + row] = w2;
    }
}

// ============================================================
// Per-batch weighted Procrustes (Horn quaternion via 4x4 Jacobi, fp64).
// ============================================================
__global__ __launch_bounds__(256) void k_proc(const float* __restrict__ src,
                                              float* __restrict__ out) {
    const int b = blockIdx.x;
    const int tid = threadIdx.x;
    __shared__ float sm[256 * 12];
    __shared__ float cent[8];
    const float* sb = src + (long)b * 3 * NN;
    const float* wb = g_W + (b << 10);
    const float* wtb = g_WT + b * 3 * NN;

    float ws = 0, s0 = 0, s1 = 0, s2 = 0, t0 = 0, t1 = 0, t2 = 0;
    for (int i = tid; i < NN; i += 256) {
        float w = wb[i];
        ws += w;
        s0 = fmaf(sb[i], w, s0);
        s1 = fmaf(sb[NN + i], w, s1);
        s2 = fmaf(sb[2 * NN + i], w, s2);
        t0 = fmaf(wtb[i], w, t0);
        t1 = fmaf(wtb[NN + i], w, t1);
        t2 = fmaf(wtb[2 * NN + i], w, t2);
    }
    sm[tid * 12 + 0] = ws; sm[tid * 12 + 1] = s0; sm[tid * 12 + 2] = s1;
    sm[tid * 12 + 3] = s2; sm[tid * 12 + 4] = t0; sm[tid * 12 + 5] = t1;
    sm[tid * 12 + 6] = t2;
    __syncthreads();
    for (int st = 128; st; st >>= 1) {
        if (tid < st)
            for (int k = 0; k < 7; ++k) sm[tid * 12 + k] += sm[(tid + st) * 12 + k];
        __syncthreads();
    }
    if (tid == 0) {
        float inv = 1.f / (sm[0] + 1e-8f);
        cent[6] = inv;
        for (int c = 0; c < 3; ++c) { cent[c] = sm[1 + c] * inv; cent[3 + c] = sm[4 + c] * inv; }
    }
    __syncthreads();
    const float inv = cent[6];
    const float sc0 = cent[0], sc1 = cent[1], sc2 = cent[2];
    const float tc0 = cent[3], tc1 = cent[4], tc2 = cent[5];

    float h[9];
#pragma unroll
    for (int k = 0; k < 9; ++k) h[k] = 0.f;
    for (int i = tid; i < NN; i += 256) {
        float wn = wb[i] * inv;
        float a0 = sb[i] - sc0, a1 = sb[NN + i] - sc1, a2 = sb[2 * NN + i] - sc2;
        float b0 = (wtb[i] - tc0) * wn;
        float b1 = (wtb[NN + i] - tc1) * wn;
        float b2 = (wtb[2 * NN + i] - tc2) * wn;
        h[0] = fmaf(a0, b0, h[0]); h[1] = fmaf(a0, b1, h[1]); h[2] = fmaf(a0, b2, h[2]);
        h[3] = fmaf(a1, b0, h[3]); h[4] = fmaf(a1, b1, h[4]); h[5] = fmaf(a1, b2, h[5]);
        h[6] = fmaf(a2, b0, h[6]); h[7] = fmaf(a2, b1, h[7]); h[8] = fmaf(a2, b2, h[8]);
    }
    __syncthreads();
    for (int k = 0; k < 9; ++k) sm[tid * 12 + k] = h[k];
    __syncthreads();
    for (int st = 128; st; st >>= 1) {
        if (tid < st)
            for (int k = 0; k < 9; ++k) sm[tid * 12 + k] += sm[(tid + st) * 12 + k];
        __syncthreads();
    }

    if (tid == 0) {
        double Sxx = sm[0], Sxy = sm[1], Sxz = sm[2];
        double Syx = sm[3], Syy = sm[4], Syz = sm[5];
        double Szx = sm[6], Szy = sm[7], Szz = sm[8];
        double A4[4][4], V4[4][4];
        A4[0][0] = Sxx + Syy + Szz;
        A4[0][1] = Syz - Szy; A4[0][2] = Szx - Sxz; A4[0][3] = Sxy - Syx;
        A4[1][1] = Sxx - Syy - Szz;
        A4[1][2] = Sxy + Syx; A4[1][3] = Szx + Sxz;
        A4[2][2] = -Sxx + Syy - Szz;
        A4[2][3] = Syz + Szy;
        A4[3][3] = -Sxx - Syy + Szz;
        A4[1][0] = A4[0][1]; A4[2][0] = A4[0][2]; A4[3][0] = A4[0][3];
        A4[2][1] = A4[1][2]; A4[3][1] = A4[1][3]; A4[3][2] = A4[2][3];
        for (int i = 0; i < 4; ++i)
            for (int j = 0; j < 4; ++j) V4[i][j] = (i == j) ? 1.0 : 0.0;
        for (int sw = 0; sw < 8; ++sw) {
            for (int p = 0; p < 3; ++p)
                for (int q = p + 1; q < 4; ++q) {
                    double apq = A4[p][q];
                    if (fabs(apq) < 1e-300) continue;
                    double tau = (A4[q][q] - A4[p][p]) / (2.0 * apq);
                    double tt = (tau >= 0 ? 1.0 : -1.0) / (fabs(tau) + sqrt(1.0 + tau * tau));
                    double cc = 1.0 / sqrt(1.0 + tt * tt);
                    double ssn = tt * cc;
                    for (int k = 0; k < 4; ++k) {
                        double r1 = A4[p][k], r2 = A4[q][k];
                        A4[p][k] = cc * r1 - ssn * r2;
                        A4[q][k] = ssn * r1 + cc * r2;
                    }
                    for (int k = 0; k < 4; ++k) {
                        double c1 = A4[k][p], c2 = A4[k][q];
                        A4[k][p] = cc * c1 - ssn * c2;
                        A4[k][q] = ssn * c1 + cc * c2;
                    }
                    for (int k = 0; k < 4; ++k) {
                        double v1 = V4[k][p], v2 = V4[k][q];
                        V4[k][p] = cc * v1 - ssn * v2;
                        V4[k][q] = ssn * v1 + cc * v2;
                    }
                }
        }
        int best = 0;
        for (int k = 1; k < 4; ++k) if (A4[k][k] > A4[best][best]) best = k;
        double q0 = V4[0][best], qx = V4[1][best], qy = V4[2][best], qz = V4[3][best];
        double qn = 1.0 / sqrt(q0 * q0 + qx * qx + qy * qy + qz * qz);
        q0 *= qn; qx *= qn; qy *= qn; qz *= qn;
        double R_[3][3];
        R_[0][0] = 1 - 2 * (qy * qy + qz * qz);
        R_[0][1] = 2 * (qx * qy - q0 * qz);
        R_[0][2] = 2 * (qx * qz + q0 * qy);
        R_[1][0] = 2 * (qx * qy + q0 * qz);
        R_[1][1] = 1 - 2 * (qx * qx + qz * qz);
        R_[1][2] = 2 * (qy * qz - q0 * qx);
        R_[2][0] = 2 * (qx * qz - q0 * qy);
        R_[2][1] = 2 * (qy * qz + q0 * qx);
        R_[2][2] = 1 - 2 * (qx * qx + qy * qy);
        double H_[3][3] = {{Sxx, Sxy, Sxz}, {Syx, Syy, Syz}, {Szx, Szy, Szz}};
        double tr1 = 0, tr2 = 0;
        for (int i = 0; i < 3; ++i)
            for (int k = 0; k < 3; ++k) {
                tr1 += R_[i][k] * H_[k][i];
                tr2 += R_[k][i] * H_[k][i];
            }
        if (tr2 > tr1) {
            for (int i = 0; i < 3; ++i)
                for (int k = i + 1; k < 3; ++k) {
                    double tmp = R_[i][k]; R_[i][k] = R_[k][i]; R_[k][i] = tmp;
                }
        }
        double scv[3] = {sc0, sc1, sc2}, tcv[3] = {tc0, tc1, tc2};
        for (int i = 0; i < 3; ++i)
            for (int k = 0; k < 3; ++k)
                out[b * 9 + i * 3 + k] = (float)R_[i][k];
        for (int c = 0; c < 3; ++c) {
            double tv = tcv[c];
            for (int k = 0; k < 3; ++k) tv -= R_[c][k] * scv[k];
            out[NB * 9 + b * 3 + c] = (float)tv;
        }
    }
}

// ============================================================
extern "C" void kernel_launch(void* const* d_in, const int* in_sizes, int n_in,
                              void* d_out, int out_size) {
    const float* srcE = (const float*)d_in[0];
    const float* tgtE = (const float*)d_in[1];
    const float* src  = (const float*)d_in[2];
    const float* tgt  = (const float*)d_in[3];
    const float* temp = (const float*)d_in[4];
    float* out = (float*)d_out;
    float* aff = out + NB * 9 + NB * 3;

    (void)in_sizes; (void)n_in; (void)out_size;

    const int SMEM_SZ = 2 * STG2;   // 81920 per CTA -> 2 CTAs/SM
    static int configured = 0;
    if (!configured) {
        cudaFuncSetAttribute(k_mma, cudaFuncAttributeMaxDynamicSharedMemorySize, SMEM_SZ);
        configured = 1;
    }

    k_conv<<<dim3(32, 16, 32), 256>>>(srcE, tgtE);
    k_mma<<<dim3(8, 8, NB), 256, SMEM_SZ>>>(temp, aff);
    for (int it = 0; it < 5; ++it) {
        k_fused<<<dim3(64, NB), 256>>>(aff, it == 0);
        k_colr<<<dim3(16, NB), 256>>>();
    }
    k_final<<<2048, 256>>>(aff, tgt);
    k_proc<<<NB, 256>>>(src, out);
}